// round 1
// baseline (speedup 1.0000x reference)
#include <cuda_runtime.h>
#include <cuda_bf16.h>
#include <math_constants.h>

// Problem constants
#define B    32
#define SX   512
#define SM_  4096
#define D    256
#define TOPK 5

// GEMM tiling
#define BM 128          // mem rows per CTA
#define BS 64           // x rows (queries) per s-chunk
#define ASTRIDE (BM + 4)   // 132 -> row stride 528B (16B aligned, bank-staggered)
#define BSTRIDE (BS + 4)   // 68  -> row stride 272B (16B aligned)

#define NEG_INF (__int_as_float(0xff800000))

// Scratch (no allocations allowed)
__device__ float g_inv_na[B * SX];
__device__ float g_inv_nb[B * SM_];
__device__ float g_simmax[B * SM_];

// ---------------------------------------------------------------------------
// 1) inverse L2 norm per row (one warp per row of 256 floats)
//    which == 0 -> x rows into g_inv_na ; which == 1 -> mem rows into g_inv_nb
// ---------------------------------------------------------------------------
__global__ void invnorm_kernel(const float* __restrict__ in, int rows, int which) {
    int gwarp = (blockIdx.x * blockDim.x + threadIdx.x) >> 5;
    int lane  = threadIdx.x & 31;
    if (gwarp >= rows) return;
    const float4* r = reinterpret_cast<const float4*>(in + (size_t)gwarp * D);
    float4 v0 = r[lane];
    float4 v1 = r[lane + 32];
    float s = v0.x * v0.x + v0.y * v0.y + v0.z * v0.z + v0.w * v0.w
            + v1.x * v1.x + v1.y * v1.y + v1.z * v1.z + v1.w * v1.w;
#pragma unroll
    for (int off = 16; off; off >>= 1)
        s += __shfl_xor_sync(0xffffffffu, s, off);
    if (lane == 0) {
        float iv = rsqrtf(s);
        if (which == 0) g_inv_na[gwarp] = iv;
        else            g_inv_nb[gwarp] = iv;
    }
}

// ---------------------------------------------------------------------------
// 2) sim_max[b, m] = max_s ( (mem[b,m,:] . x[b,s,:]) * inv_na[b,s] ) * inv_nb[b,m]
//    One CTA per (batch, 128-row mem tile). Full A tile (128x256) and a 64x256
//    B tile resident in smem -> 256-deep K loop with no inner syncs.
// ---------------------------------------------------------------------------
__global__ __launch_bounds__(256, 1)
void simmax_kernel(const float* __restrict__ x, const float* __restrict__ mem) {
    extern __shared__ float smem[];
    float* As = smem;                       // [D][ASTRIDE]  (k-major, transposed)
    float* Bs = smem + D * ASTRIDE;         // [D][BSTRIDE]

    const int tid = threadIdx.x;
    const int b   = blockIdx.y;
    const int m0  = blockIdx.x * BM;

    const float* Ag = mem + ((size_t)b * SM_ + m0) * D;
    const float* Xg = x   + (size_t)b * SX * D;

    // ---- load A tile transposed: thread handles one m row, half of K ----
    {
        const int m  = tid >> 1;            // 0..127
        const int k0 = (tid & 1) * 128;     // 0 or 128
        const float4* src = reinterpret_cast<const float4*>(Ag + m * D + k0);
#pragma unroll
        for (int kk = 0; kk < 128; kk += 4) {
            float4 v = src[kk >> 2];
            As[(k0 + kk + 0) * ASTRIDE + m] = v.x;
            As[(k0 + kk + 1) * ASTRIDE + m] = v.y;
            As[(k0 + kk + 2) * ASTRIDE + m] = v.z;
            As[(k0 + kk + 3) * ASTRIDE + m] = v.w;
        }
    }

    const int ty = tid >> 4;     // 0..15  -> rows ty*8 .. ty*8+7
    const int tx = tid & 15;     // 0..15  -> cols tx*4 .. tx*4+3

    float rmax[8];
#pragma unroll
    for (int i = 0; i < 8; ++i) rmax[i] = NEG_INF;

    for (int s0 = 0; s0 < SX; s0 += BS) {
        __syncthreads();   // protect Bs reuse from previous iteration
        // ---- load B tile transposed: 64 rows x 256 k -> Bs[k][s] ----
        {
            const int srow = tid >> 2;           // 0..63
            const int kq   = (tid & 3) * 64;     // quarter of K
            const float4* src = reinterpret_cast<const float4*>(Xg + (size_t)(s0 + srow) * D + kq);
#pragma unroll
            for (int kk = 0; kk < 64; kk += 4) {
                float4 v = src[kk >> 2];
                Bs[(kq + kk + 0) * BSTRIDE + srow] = v.x;
                Bs[(kq + kk + 1) * BSTRIDE + srow] = v.y;
                Bs[(kq + kk + 2) * BSTRIDE + srow] = v.z;
                Bs[(kq + kk + 3) * BSTRIDE + srow] = v.w;
            }
        }
        __syncthreads();

        float acc[8][4];
#pragma unroll
        for (int i = 0; i < 8; ++i)
#pragma unroll
            for (int j = 0; j < 4; ++j) acc[i][j] = 0.0f;

#pragma unroll 4
        for (int kk = 0; kk < D; ++kk) {
            const float4 a0 = *reinterpret_cast<const float4*>(&As[kk * ASTRIDE + ty * 8]);
            const float4 a1 = *reinterpret_cast<const float4*>(&As[kk * ASTRIDE + ty * 8 + 4]);
            const float4 bv = *reinterpret_cast<const float4*>(&Bs[kk * BSTRIDE + tx * 4]);
            const float a[8]  = {a0.x, a0.y, a0.z, a0.w, a1.x, a1.y, a1.z, a1.w};
            const float bb[4] = {bv.x, bv.y, bv.z, bv.w};
#pragma unroll
            for (int i = 0; i < 8; ++i)
#pragma unroll
                for (int j = 0; j < 4; ++j)
                    acc[i][j] = fmaf(a[i], bb[j], acc[i][j]);
        }

        // scale by 1/||x_s|| and fold into running max over s
#pragma unroll
        for (int j = 0; j < 4; ++j) {
            const float ina = g_inv_na[b * SX + s0 + tx * 4 + j];
#pragma unroll
            for (int i = 0; i < 8; ++i)
                rmax[i] = fmaxf(rmax[i], acc[i][j] * ina);
        }
    }

    // reduce max over the 16 tx lanes (each 16-lane group shares ty)
#pragma unroll
    for (int off = 8; off; off >>= 1)
#pragma unroll
        for (int i = 0; i < 8; ++i)
            rmax[i] = fmaxf(rmax[i], __shfl_xor_sync(0xffffffffu, rmax[i], off, 16));

    if (tx == 0) {
#pragma unroll
        for (int i = 0; i < 8; ++i) {
            const int m = m0 + ty * 8 + i;
            g_simmax[b * SM_ + m] = rmax[i] * g_inv_nb[b * SM_ + m];
        }
    }
}

// ---------------------------------------------------------------------------
// 3) top-5 per batch, gather rows, emit outputs
//    out layout (float32): 5 blocks of [B,D] (querys[:,k,:]) then [B,TOPK] idx
// ---------------------------------------------------------------------------
__global__ void topk_kernel(const float* __restrict__ mem, float* __restrict__ out) {
    __shared__ float sv[SM_];
    __shared__ float redv[256];
    __shared__ int   redi[256];
    __shared__ int   sel[TOPK];

    const int b   = blockIdx.x;
    const int tid = threadIdx.x;

    for (int i = tid; i < SM_; i += 256) sv[i] = g_simmax[b * SM_ + i];
    __syncthreads();

    for (int k = 0; k < TOPK; ++k) {
        float bv = NEG_INF;
        int   bi = 0;
        for (int i = tid; i < SM_; i += 256) {
            float v = sv[i];
            if (v > bv || (v == bv && i < bi)) { bv = v; bi = i; }
        }
        redv[tid] = bv;
        redi[tid] = bi;
        __syncthreads();
        for (int s = 128; s; s >>= 1) {
            if (tid < s) {
                float ov = redv[tid + s];
                int   oi = redi[tid + s];
                if (ov > redv[tid] || (ov == redv[tid] && oi < redi[tid])) {
                    redv[tid] = ov;
                    redi[tid] = oi;
                }
            }
            __syncthreads();
        }
        if (tid == 0) {
            sel[k] = redi[0];
            sv[redi[0]] = NEG_INF;   // exclude for next round
        }
        __syncthreads();
    }

    // gather selected memory rows: out[k*B*D + b*D + d]
    for (int k = 0; k < TOPK; ++k) {
        const float* row = mem + ((size_t)b * SM_ + sel[k]) * D;
        out[(size_t)k * B * D + (size_t)b * D + tid] = row[tid];   // tid in [0,256)
    }
    if (tid < TOPK)
        out[(size_t)TOPK * B * D + b * TOPK + tid] = (float)sel[tid];
}

// ---------------------------------------------------------------------------
extern "C" void kernel_launch(void* const* d_in, const int* in_sizes, int n_in,
                              void* d_out, int out_size) {
    const float* x   = (const float*)d_in[0];   // [B, SX, D]
    const float* mem = (const float*)d_in[1];   // [B, SM, D]
    float* out = (float*)d_out;

    (void)in_sizes; (void)n_in; (void)out_size;

    // norms
    invnorm_kernel<<<(B * SX) / 8, 256>>>(x, B * SX, 0);
    invnorm_kernel<<<(B * SM_) / 8, 256>>>(mem, B * SM_, 1);

    // sim-max GEMM
    const int smem_bytes = (D * ASTRIDE + D * BSTRIDE) * (int)sizeof(float); // ~204.8 KB
    static bool attr_set = false;  // idempotent attribute, not a cache of work
    if (!attr_set) {
        cudaFuncSetAttribute(simmax_kernel,
                             cudaFuncAttributeMaxDynamicSharedMemorySize, smem_bytes);
        attr_set = true;
    }
    dim3 grid(SM_ / BM, B);
    simmax_kernel<<<grid, 256, smem_bytes>>>(x, mem);

    // top-k + gather
    topk_kernel<<<B, 256>>>(mem, out);
}

// round 3
// speedup vs baseline: 2.5530x; 2.5530x over previous
#include <cuda_runtime.h>
#include <cuda_bf16.h>
#include <cstdint>

// Problem constants
#define B    32
#define SX   512
#define SM_  4096
#define D    256
#define TOPK 5
#define NCAND 8

#define NEG_INF (__int_as_float(0xff800000))

// GEMM tiling
#define MT   128          // mem rows per CTA
#define NC   128          // query chunk
#define NCH  (SX / NC)    // 4 chunks
#define KSTEPS (D / 16)   // 16 k-steps of 16
#define STRIDE 264        // bf16 elems per smem row (264*2=528B, 16B aligned, 4-bank stagger)

// Scratch (no allocations allowed)
__device__ float g_inv_na[B * SX];
__device__ float g_inv_nb[B * SM_];
__device__ float g_simmax[B * SM_];
__device__ int   g_cand[B * NCAND];

// ---------------------------------------------------------------------------
// helpers
// ---------------------------------------------------------------------------
__device__ __forceinline__ uint32_t smem_u32(const void* p) {
    return (uint32_t)__cvta_generic_to_shared(p);
}

__device__ __forceinline__ uint32_t pack_bf2(float a, float b) {
    __nv_bfloat162 h = __float22bfloat162_rn(make_float2(a, b));
    return *reinterpret_cast<uint32_t*>(&h);
}

__device__ __forceinline__ void ldsm_x4(uint32_t& r0, uint32_t& r1,
                                        uint32_t& r2, uint32_t& r3, uint32_t addr) {
    asm volatile("ldmatrix.sync.aligned.m8n8.x4.shared.b16 {%0,%1,%2,%3}, [%4];"
                 : "=r"(r0), "=r"(r1), "=r"(r2), "=r"(r3) : "r"(addr));
}

__device__ __forceinline__ void mma_bf16(float& c0, float& c1, float& c2, float& c3,
                                         uint32_t a0, uint32_t a1, uint32_t a2, uint32_t a3,
                                         uint32_t b0, uint32_t b1) {
    asm volatile(
        "mma.sync.aligned.m16n8k16.row.col.f32.bf16.bf16.f32 "
        "{%0,%1,%2,%3}, {%4,%5,%6,%7}, {%8,%9}, {%0,%1,%2,%3};"
        : "+f"(c0), "+f"(c1), "+f"(c2), "+f"(c3)
        : "r"(a0), "r"(a1), "r"(a2), "r"(a3), "r"(b0), "r"(b1));
}

// ---------------------------------------------------------------------------
// 1) inverse L2 norm per row (one warp per row of 256 floats)
// ---------------------------------------------------------------------------
__global__ void invnorm_kernel(const float* __restrict__ in, int rows, int which) {
    int gwarp = (blockIdx.x * blockDim.x + threadIdx.x) >> 5;
    int lane  = threadIdx.x & 31;
    if (gwarp >= rows) return;
    const float4* r = reinterpret_cast<const float4*>(in + (size_t)gwarp * D);
    float4 v0 = r[lane];
    float4 v1 = r[lane + 32];
    float s = v0.x * v0.x + v0.y * v0.y + v0.z * v0.z + v0.w * v0.w
            + v1.x * v1.x + v1.y * v1.y + v1.z * v1.z + v1.w * v1.w;
#pragma unroll
    for (int off = 16; off; off >>= 1)
        s += __shfl_xor_sync(0xffffffffu, s, off);
    if (lane == 0) {
        float iv = rsqrtf(s);
        if (which == 0) g_inv_na[gwarp] = iv;
        else            g_inv_nb[gwarp] = iv;
    }
}

// ---------------------------------------------------------------------------
// 2) tensor sim-max via mma.sync bf16: CTA = (batch, 128 mem rows) x 128-query
//    chunks. 8 warps in 4(m) x 2(n) grid; warp tile 32x64; K=256.
// ---------------------------------------------------------------------------
__global__ __launch_bounds__(256, 1)
void simmax_mma_kernel(const float* __restrict__ x, const float* __restrict__ mem) {
    extern __shared__ char smem[];
    __nv_bfloat16* sA = reinterpret_cast<__nv_bfloat16*>(smem);            // [128][STRIDE]
    __nv_bfloat16* sB = sA + MT * STRIDE;                                  // [128][STRIDE]
    float* s_ina = reinterpret_cast<float*>(sB + NC * STRIDE);             // [128]
    float* red   = s_ina + NC;                                             // [256]

    const int tid    = threadIdx.x;
    const int wid    = tid >> 5;
    const int lane   = tid & 31;
    const int b      = blockIdx.y;
    const int m0     = blockIdx.x * MT;
    const int warp_m = wid & 3;       // 0..3 -> m block of 32
    const int warp_n = wid >> 2;      // 0..1 -> n block of 64

    // ---- load + convert A tile (mem rows) ----
    {
        const float* Ag = mem + ((size_t)b * SM_ + m0) * D;
        const int r  = tid >> 1;
        const int k0 = (tid & 1) * 128;
        const float4* src = reinterpret_cast<const float4*>(Ag + (size_t)r * D + k0);
        uint4* dst = reinterpret_cast<uint4*>(sA + r * STRIDE + k0);
#pragma unroll
        for (int kk = 0; kk < 128; kk += 8) {
            float4 f0 = src[kk >> 2];
            float4 f1 = src[(kk >> 2) + 1];
            uint4 v;
            v.x = pack_bf2(f0.x, f0.y);
            v.y = pack_bf2(f0.z, f0.w);
            v.z = pack_bf2(f1.x, f1.y);
            v.w = pack_bf2(f1.z, f1.w);
            dst[kk >> 3] = v;
        }
    }

    // precompute ldmatrix lane addresses
    const int g = lane >> 3, r8 = lane & 7;
    // A (x4 covers one 16x16 m-tile): row = mbase + (g&1)*8 + r8, k = kbase + (g>>1)*8
    const uint32_t aA = smem_u32(sA) +
        (uint32_t)(((warp_m * 32 + (g & 1) * 8 + r8) * STRIDE + (g >> 1) * 8) * 2);
    // B (x4 covers two adjacent 8-n tiles): row = nbase + (g>>1)*8 + r8, k = kbase + (g&1)*8
    const uint32_t aB = smem_u32(sB) +
        (uint32_t)(((warp_n * 64 + (g >> 1) * 8 + r8) * STRIDE + (g & 1) * 8) * 2);

    float rmax[2][2];
#pragma unroll
    for (int i = 0; i < 2; ++i) rmax[i][0] = rmax[i][1] = NEG_INF;

    for (int c = 0; c < NCH; ++c) {
        __syncthreads();   // previous chunk's reads complete before overwrite
        // ---- load + convert B chunk (x rows) ----
        {
            const int s0 = c * NC;
            const int r  = tid >> 1;
            const int k0 = (tid & 1) * 128;
            const float4* src = reinterpret_cast<const float4*>(
                x + ((size_t)b * SX + s0 + r) * D + k0);
            uint4* dst = reinterpret_cast<uint4*>(sB + r * STRIDE + k0);
#pragma unroll
            for (int kk = 0; kk < 128; kk += 8) {
                float4 f0 = src[kk >> 2];
                float4 f1 = src[(kk >> 2) + 1];
                uint4 v;
                v.x = pack_bf2(f0.x, f0.y);
                v.y = pack_bf2(f0.z, f0.w);
                v.z = pack_bf2(f1.x, f1.y);
                v.w = pack_bf2(f1.z, f1.w);
                dst[kk >> 3] = v;
            }
            if (tid < NC) s_ina[tid] = g_inv_na[b * SX + s0 + tid];
        }
        __syncthreads();

        float acc[2][8][4];
#pragma unroll
        for (int mt = 0; mt < 2; ++mt)
#pragma unroll
            for (int nt = 0; nt < 8; ++nt)
#pragma unroll
                for (int q = 0; q < 4; ++q) acc[mt][nt][q] = 0.0f;

#pragma unroll 4
        for (int ks = 0; ks < KSTEPS; ++ks) {
            const uint32_t koff = (uint32_t)(ks * 16 * 2);
            uint32_t a[2][4];
#pragma unroll
            for (int mt = 0; mt < 2; ++mt)
                ldsm_x4(a[mt][0], a[mt][1], a[mt][2], a[mt][3],
                        aA + (uint32_t)(mt * 16 * STRIDE * 2) + koff);
            uint32_t bfr[8][2];
#pragma unroll
            for (int p = 0; p < 4; ++p) {
                uint32_t r0, r1, r2, r3;
                ldsm_x4(r0, r1, r2, r3,
                        aB + (uint32_t)(p * 16 * STRIDE * 2) + koff);
                bfr[p * 2][0]     = r0; bfr[p * 2][1]     = r1;
                bfr[p * 2 + 1][0] = r2; bfr[p * 2 + 1][1] = r3;
            }
#pragma unroll
            for (int mt = 0; mt < 2; ++mt)
#pragma unroll
                for (int nt = 0; nt < 8; ++nt)
                    mma_bf16(acc[mt][nt][0], acc[mt][nt][1],
                             acc[mt][nt][2], acc[mt][nt][3],
                             a[mt][0], a[mt][1], a[mt][2], a[mt][3],
                             bfr[nt][0], bfr[nt][1]);
        }

        // ---- fold chunk into running max (scale by 1/||x_s|| first) ----
#pragma unroll
        for (int nt = 0; nt < 8; ++nt) {
            const int n0 = warp_n * 64 + nt * 8 + (lane & 3) * 2;
            const float i0 = s_ina[n0], i1 = s_ina[n0 + 1];
#pragma unroll
            for (int mt = 0; mt < 2; ++mt) {
                rmax[mt][0] = fmaxf(rmax[mt][0],
                                    fmaxf(acc[mt][nt][0] * i0, acc[mt][nt][1] * i1));
                rmax[mt][1] = fmaxf(rmax[mt][1],
                                    fmaxf(acc[mt][nt][2] * i0, acc[mt][nt][3] * i1));
            }
        }
    }

    // reduce over the 4 lanes sharing each m row (lane&3), then across warp_n
#pragma unroll
    for (int mt = 0; mt < 2; ++mt)
#pragma unroll
        for (int rh = 0; rh < 2; ++rh) {
            float v = rmax[mt][rh];
            v = fmaxf(v, __shfl_xor_sync(0xffffffffu, v, 1));
            v = fmaxf(v, __shfl_xor_sync(0xffffffffu, v, 2));
            rmax[mt][rh] = v;
        }
    __syncthreads();
    if ((lane & 3) == 0) {
#pragma unroll
        for (int mt = 0; mt < 2; ++mt)
#pragma unroll
            for (int rh = 0; rh < 2; ++rh) {
                const int m = warp_m * 32 + mt * 16 + rh * 8 + (lane >> 2);
                red[warp_n * MT + m] = rmax[mt][rh];
            }
    }
    __syncthreads();
    if (tid < MT) {
        float v = fmaxf(red[tid], red[MT + tid]);
        const int m = m0 + tid;
        g_simmax[b * SM_ + m] = v * g_inv_nb[b * SM_ + m];
    }
}

// ---------------------------------------------------------------------------
// 3) approx top-8 candidates per batch (bf16-accurate sims; margin >> error)
// ---------------------------------------------------------------------------
__global__ void top8_kernel() {
    __shared__ float sv[SM_];
    __shared__ float redv[256];
    __shared__ int   redi[256];

    const int b   = blockIdx.x;
    const int tid = threadIdx.x;

    for (int i = tid; i < SM_; i += 256) sv[i] = g_simmax[b * SM_ + i];
    __syncthreads();

    for (int k = 0; k < NCAND; ++k) {
        float bv = NEG_INF;
        int   bi = 0;
        for (int i = tid; i < SM_; i += 256) {
            float v = sv[i];
            if (v > bv || (v == bv && i < bi)) { bv = v; bi = i; }
        }
        redv[tid] = bv;
        redi[tid] = bi;
        __syncthreads();
        for (int s = 128; s; s >>= 1) {
            if (tid < s) {
                float ov = redv[tid + s];
                int   oi = redi[tid + s];
                if (ov > redv[tid] || (ov == redv[tid] && oi < redi[tid])) {
                    redv[tid] = ov;
                    redi[tid] = oi;
                }
            }
            __syncthreads();
        }
        if (tid == 0) {
            g_cand[b * NCAND + k] = redi[0];
            sv[redi[0]] = NEG_INF;
        }
        __syncthreads();
    }
}

// ---------------------------------------------------------------------------
// 4) exact fp32 re-rank of the 8 candidates, pick top-5, gather rows + indices
//    out layout (float32): 5 blocks of [B,D] then [B,TOPK] indices
// ---------------------------------------------------------------------------
__global__ __launch_bounds__(256)
void rerank_kernel(const float* __restrict__ x, const float* __restrict__ mem,
                   float* __restrict__ out) {
    __shared__ float s_m[NCAND][D];
    __shared__ float s_x[32][D + 1];
    __shared__ float s_score[NCAND];
    __shared__ int   s_sel[TOPK];

    const int b    = blockIdx.x;
    const int tid  = threadIdx.x;
    const int wid  = tid >> 5;
    const int lane = tid & 31;

    for (int i = tid; i < NCAND * D; i += 256) {
        int c = i >> 8, d = i & 255;
        s_m[c][d] = mem[((size_t)b * SM_ + g_cand[b * NCAND + c]) * D + d];
    }

    float vmax = NEG_INF;
    for (int s0 = 0; s0 < SX; s0 += 32) {
        __syncthreads();
        for (int i = tid; i < 32 * D; i += 256) {
            int r = i >> 8, d = i & 255;
            s_x[r][d] = x[((size_t)b * SX + s0 + r) * D + d];
        }
        __syncthreads();
        float dot = 0.0f;
#pragma unroll 8
        for (int d = 0; d < D; ++d)
            dot = fmaf(s_x[lane][d], s_m[wid][d], dot);
        vmax = fmaxf(vmax, dot * g_inv_na[b * SX + s0 + lane]);
    }
#pragma unroll
    for (int off = 16; off; off >>= 1)
        vmax = fmaxf(vmax, __shfl_xor_sync(0xffffffffu, vmax, off));
    if (lane == 0)
        s_score[wid] = vmax * g_inv_nb[b * SM_ + g_cand[b * NCAND + wid]];
    __syncthreads();

    if (tid == 0) {
        float sc[NCAND];
        int   ix[NCAND];
        for (int i = 0; i < NCAND; ++i) {
            sc[i] = s_score[i];
            ix[i] = g_cand[b * NCAND + i];
        }
        for (int k = 0; k < TOPK; ++k) {
            int best = k;
            for (int j = k + 1; j < NCAND; ++j)
                if (sc[j] > sc[best] || (sc[j] == sc[best] && ix[j] < ix[best])) best = j;
            float ts = sc[k]; sc[k] = sc[best]; sc[best] = ts;
            int   ti = ix[k]; ix[k] = ix[best]; ix[best] = ti;
            s_sel[k] = ix[k];
        }
    }
    __syncthreads();

    for (int k = 0; k < TOPK; ++k)
        out[(size_t)k * B * D + (size_t)b * D + tid] =
            mem[((size_t)b * SM_ + s_sel[k]) * D + tid];
    if (tid < TOPK)
        out[(size_t)TOPK * B * D + b * TOPK + tid] = (float)s_sel[tid];
}

// ---------------------------------------------------------------------------
extern "C" void kernel_launch(void* const* d_in, const int* in_sizes, int n_in,
                              void* d_out, int out_size) {
    const float* x   = (const float*)d_in[0];   // [B, SX, D]
    const float* mem = (const float*)d_in[1];   // [B, SM, D]
    float* out = (float*)d_out;
    (void)in_sizes; (void)n_in; (void)out_size;

    invnorm_kernel<<<(B * SX) / 8, 256>>>(x, B * SX, 0);
    invnorm_kernel<<<(B * SM_) / 8, 256>>>(mem, B * SM_, 1);

    const int smem_bytes = (MT * STRIDE + NC * STRIDE) * 2 + (NC + 256) * 4; // ~136.7 KB
    static bool attr_set = false;   // idempotent attribute, not work caching
    if (!attr_set) {
        cudaFuncSetAttribute(simmax_mma_kernel,
                             cudaFuncAttributeMaxDynamicSharedMemorySize, smem_bytes);
        attr_set = true;
    }
    dim3 grid(SM_ / MT, B);
    simmax_mma_kernel<<<grid, 256, smem_bytes>>>(x, mem);

    top8_kernel<<<B, 256>>>();
    rerank_kernel<<<B, 256>>>(x, mem, out);
}

// round 4
// speedup vs baseline: 4.1374x; 1.6206x over previous
#include <cuda_runtime.h>
#include <cuda_bf16.h>
#include <cstdint>

// Problem constants
#define B    32
#define SX   512
#define SM_  4096
#define D    256
#define TOPK 5
#define NCAND 8

#define NEG_INF (__int_as_float(0xff800000))

// GEMM tiling
#define MT   128          // mem rows per CTA
#define NC   128          // query chunk
#define NCH  (SX / NC)    // 4 chunks
#define KSTEPS (D / 16)   // 16 k-steps of 16
#define STRIDE 264        // bf16 elems per smem row (528B: 16B aligned, 4-bank stagger)

// Scratch (no allocations allowed)
__device__ float g_inv_na[B * SX];
__device__ float g_inv_nb[B * SM_];
__device__ float g_simmax[B * SM_];
__device__ int   g_cand[B * NCAND];
__device__ __nv_bfloat16 g_xbf[B * SX * D];    // 8 MB
__device__ __nv_bfloat16 g_mbf[B * SM_ * D];   // 64 MB

// ---------------------------------------------------------------------------
// helpers
// ---------------------------------------------------------------------------
__device__ __forceinline__ uint32_t smem_u32(const void* p) {
    return (uint32_t)__cvta_generic_to_shared(p);
}

__device__ __forceinline__ uint32_t pack_bf2(float a, float b) {
    __nv_bfloat162 h = __float22bfloat162_rn(make_float2(a, b));
    return *reinterpret_cast<uint32_t*>(&h);
}

__device__ __forceinline__ void cp16(uint32_t dst, const void* src) {
    asm volatile("cp.async.cg.shared.global [%0], [%1], 16;" :: "r"(dst), "l"(src));
}
__device__ __forceinline__ void cp_commit() {
    asm volatile("cp.async.commit_group;" ::: "memory");
}
__device__ __forceinline__ void cp_wait0() {
    asm volatile("cp.async.wait_group 0;" ::: "memory");
}

__device__ __forceinline__ void ldsm_x4(uint32_t& r0, uint32_t& r1,
                                        uint32_t& r2, uint32_t& r3, uint32_t addr) {
    asm volatile("ldmatrix.sync.aligned.m8n8.x4.shared.b16 {%0,%1,%2,%3}, [%4];"
                 : "=r"(r0), "=r"(r1), "=r"(r2), "=r"(r3) : "r"(addr));
}

__device__ __forceinline__ void mma_bf16(float& c0, float& c1, float& c2, float& c3,
                                         uint32_t a0, uint32_t a1, uint32_t a2, uint32_t a3,
                                         uint32_t b0, uint32_t b1) {
    asm volatile(
        "mma.sync.aligned.m16n8k16.row.col.f32.bf16.bf16.f32 "
        "{%0,%1,%2,%3}, {%4,%5,%6,%7}, {%8,%9}, {%0,%1,%2,%3};"
        : "+f"(c0), "+f"(c1), "+f"(c2), "+f"(c3)
        : "r"(a0), "r"(a1), "r"(a2), "r"(a3), "r"(b0), "r"(b1));
}

// ---------------------------------------------------------------------------
// 1) inverse L2 norm per row + bf16 conversion (one warp per row of 256 floats)
//    which == 0 -> x (g_inv_na, g_xbf) ; which == 1 -> mem (g_inv_nb, g_mbf)
// ---------------------------------------------------------------------------
__global__ void invnorm_kernel(const float* __restrict__ in, int rows, int which) {
    int gwarp = (blockIdx.x * blockDim.x + threadIdx.x) >> 5;
    int lane  = threadIdx.x & 31;
    if (gwarp >= rows) return;
    const float4* r = reinterpret_cast<const float4*>(in + (size_t)gwarp * D);
    float4 v0 = r[lane];
    float4 v1 = r[lane + 32];

    __nv_bfloat16* dst = (which ? g_mbf : g_xbf) + (size_t)gwarp * D;
    uint2 w0 = make_uint2(pack_bf2(v0.x, v0.y), pack_bf2(v0.z, v0.w));
    uint2 w1 = make_uint2(pack_bf2(v1.x, v1.y), pack_bf2(v1.z, v1.w));
    reinterpret_cast<uint2*>(dst)[lane]      = w0;
    reinterpret_cast<uint2*>(dst)[lane + 32] = w1;

    float s = v0.x * v0.x + v0.y * v0.y + v0.z * v0.z + v0.w * v0.w
            + v1.x * v1.x + v1.y * v1.y + v1.z * v1.z + v1.w * v1.w;
#pragma unroll
    for (int off = 16; off; off >>= 1)
        s += __shfl_xor_sync(0xffffffffu, s, off);
    if (lane == 0) {
        float iv = rsqrtf(s);
        if (which == 0) g_inv_na[gwarp] = iv;
        else            g_inv_nb[gwarp] = iv;
    }
}

// ---------------------------------------------------------------------------
// 2) tensor sim-max via mma.sync bf16, double-buffered cp.async B chunks.
//    CTA = (batch, 128 mem rows); 8 warps in 4(m) x 2(n); warp tile 32x64; K=256.
// ---------------------------------------------------------------------------
__device__ __forceinline__ void load_tile_async(uint32_t sdst,
                                                const __nv_bfloat16* gsrc, int tid) {
    // 128 rows x 512B, padded stride 528B; 16B per cp.async
#pragma unroll
    for (int i = tid; i < MT * 32; i += 256) {
        const int r = i >> 5, c = i & 31;
        cp16(sdst + (uint32_t)(r * (STRIDE * 2) + c * 16), gsrc + (size_t)r * D + c * 8);
    }
}

__global__ __launch_bounds__(256, 1)
void simmax_mma_kernel(const float* __restrict__ x_unused) {
    extern __shared__ char smem[];
    __nv_bfloat16* sA  = reinterpret_cast<__nv_bfloat16*>(smem);   // [128][STRIDE]
    __nv_bfloat16* sB0 = sA + MT * STRIDE;
    __nv_bfloat16* sB1 = sB0 + NC * STRIDE;
    float* s_ina = reinterpret_cast<float*>(sB1 + NC * STRIDE);    // [512]
    float* red   = s_ina + SX;                                     // [256]

    const int tid    = threadIdx.x;
    const int wid    = tid >> 5;
    const int lane   = tid & 31;
    const int b      = blockIdx.y;
    const int m0     = blockIdx.x * MT;
    const int warp_m = wid & 3;
    const int warp_n = wid >> 2;

    const __nv_bfloat16* Ag = g_mbf + ((size_t)b * SM_ + m0) * D;
    const __nv_bfloat16* Xg = g_xbf + (size_t)b * SX * D;

    // prologue: A tile + B chunk 0 in flight
    load_tile_async(smem_u32(sA), Ag, tid);
    cp_commit();
    load_tile_async(smem_u32(sB0), Xg, tid);
    cp_commit();
#pragma unroll
    for (int i = tid; i < SX; i += 256) s_ina[i] = g_inv_na[b * SX + i];
    cp_wait0();
    __syncthreads();

    // ldmatrix lane addresses
    const int g = lane >> 3, r8 = lane & 7;
    const uint32_t aA = smem_u32(sA) +
        (uint32_t)(((warp_m * 32 + (g & 1) * 8 + r8) * STRIDE + (g >> 1) * 8) * 2);
    const uint32_t aBoff =
        (uint32_t)(((warp_n * 64 + (g >> 1) * 8 + r8) * STRIDE + (g & 1) * 8) * 2);
    const uint32_t aBbuf[2] = { smem_u32(sB0) + aBoff, smem_u32(sB1) + aBoff };
    const uint32_t sBbuf[2] = { smem_u32(sB0), smem_u32(sB1) };

    float rmax[2][2];
#pragma unroll
    for (int i = 0; i < 2; ++i) rmax[i][0] = rmax[i][1] = NEG_INF;

    for (int c = 0; c < NCH; ++c) {
        // prefetch next chunk into the other buffer
        if (c + 1 < NCH) {
            load_tile_async(sBbuf[(c + 1) & 1], Xg + (size_t)(c + 1) * NC * D, tid);
            cp_commit();
        }

        const uint32_t aB = aBbuf[c & 1];
        float acc[2][8][4];
#pragma unroll
        for (int mt = 0; mt < 2; ++mt)
#pragma unroll
            for (int nt = 0; nt < 8; ++nt)
#pragma unroll
                for (int q = 0; q < 4; ++q) acc[mt][nt][q] = 0.0f;

#pragma unroll 4
        for (int ks = 0; ks < KSTEPS; ++ks) {
            const uint32_t koff = (uint32_t)(ks * 16 * 2);
            uint32_t a[2][4];
#pragma unroll
            for (int mt = 0; mt < 2; ++mt)
                ldsm_x4(a[mt][0], a[mt][1], a[mt][2], a[mt][3],
                        aA + (uint32_t)(mt * 16 * STRIDE * 2) + koff);
            uint32_t bfr[8][2];
#pragma unroll
            for (int p = 0; p < 4; ++p) {
                uint32_t r0, r1, r2, r3;
                ldsm_x4(r0, r1, r2, r3,
                        aB + (uint32_t)(p * 16 * STRIDE * 2) + koff);
                bfr[p * 2][0]     = r0; bfr[p * 2][1]     = r1;
                bfr[p * 2 + 1][0] = r2; bfr[p * 2 + 1][1] = r3;
            }
#pragma unroll
            for (int mt = 0; mt < 2; ++mt)
#pragma unroll
                for (int nt = 0; nt < 8; ++nt)
                    mma_bf16(acc[mt][nt][0], acc[mt][nt][1],
                             acc[mt][nt][2], acc[mt][nt][3],
                             a[mt][0], a[mt][1], a[mt][2], a[mt][3],
                             bfr[nt][0], bfr[nt][1]);
        }

        // fold chunk into running max (scale by 1/||x_s||)
#pragma unroll
        for (int nt = 0; nt < 8; ++nt) {
            const int n0 = c * NC + warp_n * 64 + nt * 8 + (lane & 3) * 2;
            const float i0 = s_ina[n0], i1 = s_ina[n0 + 1];
#pragma unroll
            for (int mt = 0; mt < 2; ++mt) {
                rmax[mt][0] = fmaxf(rmax[mt][0],
                                    fmaxf(acc[mt][nt][0] * i0, acc[mt][nt][1] * i1));
                rmax[mt][1] = fmaxf(rmax[mt][1],
                                    fmaxf(acc[mt][nt][2] * i0, acc[mt][nt][3] * i1));
            }
        }

        if (c + 1 < NCH) {
            cp_wait0();
            __syncthreads();   // next buffer visible to all warps
        }
    }

    // reduce over 4 lanes sharing each m row, then across warp_n halves
#pragma unroll
    for (int mt = 0; mt < 2; ++mt)
#pragma unroll
        for (int rh = 0; rh < 2; ++rh) {
            float v = rmax[mt][rh];
            v = fmaxf(v, __shfl_xor_sync(0xffffffffu, v, 1));
            v = fmaxf(v, __shfl_xor_sync(0xffffffffu, v, 2));
            rmax[mt][rh] = v;
        }
    __syncthreads();
    if ((lane & 3) == 0) {
#pragma unroll
        for (int mt = 0; mt < 2; ++mt)
#pragma unroll
            for (int rh = 0; rh < 2; ++rh) {
                const int m = warp_m * 32 + mt * 16 + rh * 8 + (lane >> 2);
                red[warp_n * MT + m] = rmax[mt][rh];
            }
    }
    __syncthreads();
    if (tid < MT) {
        float v = fmaxf(red[tid], red[MT + tid]);
        const int m = m0 + tid;
        g_simmax[b * SM_ + m] = v * g_inv_nb[b * SM_ + m];
    }
}

// ---------------------------------------------------------------------------
// 3) approx top-8 per batch: register-resident, warp-shuffle argmax rounds
// ---------------------------------------------------------------------------
__global__ __launch_bounds__(512)
void top8_kernel() {
    __shared__ float swv[16];
    __shared__ int   swi[16];
    __shared__ int   s_win;

    const int b    = blockIdx.x;
    const int tid  = threadIdx.x;
    const int wid  = tid >> 5;
    const int lane = tid & 31;

    float e[8];
#pragma unroll
    for (int j = 0; j < 8; ++j) e[j] = g_simmax[b * SM_ + tid * 8 + j];

    for (int k = 0; k < NCAND; ++k) {
        float bv = e[0];
        int   bi = tid * 8;
#pragma unroll
        for (int j = 1; j < 8; ++j)
            if (e[j] > bv) { bv = e[j]; bi = tid * 8 + j; }   // ascending j: ties keep lower
#pragma unroll
        for (int off = 16; off; off >>= 1) {
            float ov = __shfl_xor_sync(0xffffffffu, bv, off);
            int   oi = __shfl_xor_sync(0xffffffffu, bi, off);
            if (ov > bv || (ov == bv && oi < bi)) { bv = ov; bi = oi; }
        }
        if (lane == 0) { swv[wid] = bv; swi[wid] = bi; }
        __syncthreads();
        if (wid == 0) {
            float fv = (lane < 16) ? swv[lane] : NEG_INF;
            int   fi = (lane < 16) ? swi[lane] : 0x7fffffff;
#pragma unroll
            for (int off = 8; off; off >>= 1) {
                float ov = __shfl_xor_sync(0xffffffffu, fv, off);
                int   oi = __shfl_xor_sync(0xffffffffu, fi, off);
                if (ov > fv || (ov == fv && oi < fi)) { fv = ov; fi = oi; }
            }
            if (lane == 0) {
                s_win = fi;
                g_cand[b * NCAND + k] = fi;
            }
        }
        __syncthreads();
        const int w = s_win;
        if ((w >> 3) == tid) e[w & 7] = NEG_INF;
    }
}

// ---------------------------------------------------------------------------
// 4) exact fp32 re-rank of the 8 candidates, pick top-5, gather rows + indices
//    out layout (float32): 5 blocks of [B,D] then [B,TOPK] indices
// ---------------------------------------------------------------------------
__global__ __launch_bounds__(256)
void rerank_kernel(const float* __restrict__ x, const float* __restrict__ mem,
                   float* __restrict__ out) {
    __shared__ float s_m[NCAND][D];
    __shared__ float s_x[32][D + 1];
    __shared__ float s_score[NCAND];
    __shared__ int   s_sel[TOPK];

    const int b    = blockIdx.x;
    const int tid  = threadIdx.x;
    const int wid  = tid >> 5;
    const int lane = tid & 31;

    for (int i = tid; i < NCAND * D; i += 256) {
        int c = i >> 8, d = i & 255;
        s_m[c][d] = mem[((size_t)b * SM_ + g_cand[b * NCAND + c]) * D + d];
    }

    float vmax = NEG_INF;
    for (int s0 = 0; s0 < SX; s0 += 32) {
        __syncthreads();
        for (int i = tid; i < 32 * D; i += 256) {
            int r = i >> 8, d = i & 255;
            s_x[r][d] = x[((size_t)b * SX + s0 + r) * D + d];
        }
        __syncthreads();
        float dot = 0.0f;
#pragma unroll 8
        for (int d = 0; d < D; ++d)
            dot = fmaf(s_x[lane][d], s_m[wid][d], dot);
        vmax = fmaxf(vmax, dot * g_inv_na[b * SX + s0 + lane]);
    }
#pragma unroll
    for (int off = 16; off; off >>= 1)
        vmax = fmaxf(vmax, __shfl_xor_sync(0xffffffffu, vmax, off));
    if (lane == 0)
        s_score[wid] = vmax * g_inv_nb[b * SM_ + g_cand[b * NCAND + wid]];
    __syncthreads();

    if (tid == 0) {
        float sc[NCAND];
        int   ix[NCAND];
        for (int i = 0; i < NCAND; ++i) {
            sc[i] = s_score[i];
            ix[i] = g_cand[b * NCAND + i];
        }
        for (int k = 0; k < TOPK; ++k) {
            int best = k;
            for (int j = k + 1; j < NCAND; ++j)
                if (sc[j] > sc[best] || (sc[j] == sc[best] && ix[j] < ix[best])) best = j;
            float ts = sc[k]; sc[k] = sc[best]; sc[best] = ts;
            int   ti = ix[k]; ix[k] = ix[best]; ix[best] = ti;
            s_sel[k] = ix[k];
        }
    }
    __syncthreads();

    for (int k = 0; k < TOPK; ++k)
        out[(size_t)k * B * D + (size_t)b * D + tid] =
            mem[((size_t)b * SM_ + s_sel[k]) * D + tid];
    if (tid < TOPK)
        out[(size_t)TOPK * B * D + b * TOPK + tid] = (float)s_sel[tid];
}

// ---------------------------------------------------------------------------
extern "C" void kernel_launch(void* const* d_in, const int* in_sizes, int n_in,
                              void* d_out, int out_size) {
    const float* x   = (const float*)d_in[0];   // [B, SX, D]
    const float* mem = (const float*)d_in[1];   // [B, SM, D]
    float* out = (float*)d_out;
    (void)in_sizes; (void)n_in; (void)out_size;

    invnorm_kernel<<<(B * SX) / 8, 256>>>(x, B * SX, 0);
    invnorm_kernel<<<(B * SM_) / 8, 256>>>(mem, B * SM_, 1);

    const int smem_bytes = (MT * STRIDE + 2 * NC * STRIDE) * 2 + (SX + 256) * 4; // ~205.8 KB
    static bool attr_set = false;   // idempotent attribute, not work caching
    if (!attr_set) {
        cudaFuncSetAttribute(simmax_mma_kernel,
                             cudaFuncAttributeMaxDynamicSharedMemorySize, smem_bytes);
        attr_set = true;
    }
    dim3 grid(SM_ / MT, B);
    simmax_mma_kernel<<<grid, 256, smem_bytes>>>(x);

    top8_kernel<<<B, 512>>>();
    rerank_kernel<<<B, 256>>>(x, mem, out);
}

// round 5
// speedup vs baseline: 4.1843x; 1.0113x over previous
#include <cuda_runtime.h>
#include <cuda_bf16.h>
#include <cstdint>

// Problem constants
#define B    32
#define SX   512
#define SM_  4096
#define D    256
#define TOPK 5
#define NCAND 8

#define NEG_INF (__int_as_float(0xff800000))

// GEMM tiling
#define MT   128          // mem rows per CTA
#define NC   128          // query chunk
#define NCH  (SX / NC)    // 4 chunks
#define KSTEPS (D / 16)   // 16 k-steps of 16
#define STRIDE 264        // bf16 elems per smem row (528B: 16B aligned, 4-bank stagger)
#define NTHREADS 512

// Scratch (no allocations allowed)
__device__ float g_inv_na[B * SX];
__device__ float g_inv_nb[B * SM_];
__device__ float g_simmax[B * SM_];
__device__ int   g_cand[B * NCAND];
__device__ __nv_bfloat16 g_xbf[B * SX * D];    // 8 MB
__device__ __nv_bfloat16 g_mbf[B * SM_ * D];   // 64 MB

// ---------------------------------------------------------------------------
// helpers
// ---------------------------------------------------------------------------
__device__ __forceinline__ uint32_t smem_u32(const void* p) {
    return (uint32_t)__cvta_generic_to_shared(p);
}

__device__ __forceinline__ uint32_t pack_bf2(float a, float b) {
    __nv_bfloat162 h = __float22bfloat162_rn(make_float2(a, b));
    return *reinterpret_cast<uint32_t*>(&h);
}

__device__ __forceinline__ void cp16(uint32_t dst, const void* src) {
    asm volatile("cp.async.cg.shared.global [%0], [%1], 16;" :: "r"(dst), "l"(src));
}
__device__ __forceinline__ void cp_commit() {
    asm volatile("cp.async.commit_group;" ::: "memory");
}
__device__ __forceinline__ void cp_wait0() {
    asm volatile("cp.async.wait_group 0;" ::: "memory");
}

__device__ __forceinline__ void ldsm_x4(uint32_t& r0, uint32_t& r1,
                                        uint32_t& r2, uint32_t& r3, uint32_t addr) {
    asm volatile("ldmatrix.sync.aligned.m8n8.x4.shared.b16 {%0,%1,%2,%3}, [%4];"
                 : "=r"(r0), "=r"(r1), "=r"(r2), "=r"(r3) : "r"(addr));
}

__device__ __forceinline__ void mma_bf16(float& c0, float& c1, float& c2, float& c3,
                                         uint32_t a0, uint32_t a1, uint32_t a2, uint32_t a3,
                                         uint32_t b0, uint32_t b1) {
    asm volatile(
        "mma.sync.aligned.m16n8k16.row.col.f32.bf16.bf16.f32 "
        "{%0,%1,%2,%3}, {%4,%5,%6,%7}, {%8,%9}, {%0,%1,%2,%3};"
        : "+f"(c0), "+f"(c1), "+f"(c2), "+f"(c3)
        : "r"(a0), "r"(a1), "r"(a2), "r"(a3), "r"(b0), "r"(b1));
}

// ---------------------------------------------------------------------------
// 1) inverse L2 norm per row + bf16 conversion (one warp per row of 256 floats)
// ---------------------------------------------------------------------------
__global__ void invnorm_kernel(const float* __restrict__ in, int rows, int which) {
    int gwarp = (blockIdx.x * blockDim.x + threadIdx.x) >> 5;
    int lane  = threadIdx.x & 31;
    if (gwarp >= rows) return;
    const float4* r = reinterpret_cast<const float4*>(in + (size_t)gwarp * D);
    float4 v0 = r[lane];
    float4 v1 = r[lane + 32];

    __nv_bfloat16* dst = (which ? g_mbf : g_xbf) + (size_t)gwarp * D;
    uint2 w0 = make_uint2(pack_bf2(v0.x, v0.y), pack_bf2(v0.z, v0.w));
    uint2 w1 = make_uint2(pack_bf2(v1.x, v1.y), pack_bf2(v1.z, v1.w));
    reinterpret_cast<uint2*>(dst)[lane]      = w0;
    reinterpret_cast<uint2*>(dst)[lane + 32] = w1;

    float s = v0.x * v0.x + v0.y * v0.y + v0.z * v0.z + v0.w * v0.w
            + v1.x * v1.x + v1.y * v1.y + v1.z * v1.z + v1.w * v1.w;
#pragma unroll
    for (int off = 16; off; off >>= 1)
        s += __shfl_xor_sync(0xffffffffu, s, off);
    if (lane == 0) {
        float iv = rsqrtf(s);
        if (which == 0) g_inv_na[gwarp] = iv;
        else            g_inv_nb[gwarp] = iv;
    }
}

// ---------------------------------------------------------------------------
// 2) tensor sim-max via mma.sync bf16, 512 threads (4 warps/SMSP), 4x4 warp
//    grid, warp tile 32x32, double-buffered cp.async B chunks.
// ---------------------------------------------------------------------------
__device__ __forceinline__ void load_tile_async(uint32_t sdst,
                                                const __nv_bfloat16* gsrc, int tid) {
    // 128 rows x 512B, padded stride 528B; 16B per cp.async
#pragma unroll
    for (int i = tid; i < MT * 32; i += NTHREADS) {
        const int r = i >> 5, c = i & 31;
        cp16(sdst + (uint32_t)(r * (STRIDE * 2) + c * 16), gsrc + (size_t)r * D + c * 8);
    }
}

__global__ __launch_bounds__(NTHREADS, 1)
void simmax_mma_kernel() {
    extern __shared__ char smem[];
    __nv_bfloat16* sA  = reinterpret_cast<__nv_bfloat16*>(smem);   // [128][STRIDE]
    __nv_bfloat16* sB0 = sA + MT * STRIDE;
    __nv_bfloat16* sB1 = sB0 + NC * STRIDE;
    float* s_ina = reinterpret_cast<float*>(sB1 + NC * STRIDE);    // [512]
    float* red   = s_ina + SX;                                     // [4*128]

    const int tid    = threadIdx.x;
    const int wid    = tid >> 5;
    const int lane   = tid & 31;
    const int b      = blockIdx.y;
    const int m0     = blockIdx.x * MT;
    const int warp_m = wid & 3;       // m block of 32
    const int warp_n = wid >> 2;      // n block of 32 (0..3)

    const __nv_bfloat16* Ag = g_mbf + ((size_t)b * SM_ + m0) * D;
    const __nv_bfloat16* Xg = g_xbf + (size_t)b * SX * D;

    // prologue: A tile + B chunk 0 in flight
    load_tile_async(smem_u32(sA), Ag, tid);
    cp_commit();
    load_tile_async(smem_u32(sB0), Xg, tid);
    cp_commit();
#pragma unroll
    for (int i = tid; i < SX; i += NTHREADS) s_ina[i] = g_inv_na[b * SX + i];
    cp_wait0();
    __syncthreads();

    // ldmatrix lane addresses
    const int g = lane >> 3, r8 = lane & 7;
    const uint32_t aA = smem_u32(sA) +
        (uint32_t)(((warp_m * 32 + (g & 1) * 8 + r8) * STRIDE + (g >> 1) * 8) * 2);
    const uint32_t aBoff =
        (uint32_t)(((warp_n * 32 + (g >> 1) * 8 + r8) * STRIDE + (g & 1) * 8) * 2);
    const uint32_t aBbuf[2] = { smem_u32(sB0) + aBoff, smem_u32(sB1) + aBoff };
    const uint32_t sBbuf[2] = { smem_u32(sB0), smem_u32(sB1) };

    float rmax[2][2];
#pragma unroll
    for (int i = 0; i < 2; ++i) rmax[i][0] = rmax[i][1] = NEG_INF;

    for (int c = 0; c < NCH; ++c) {
        if (c + 1 < NCH) {
            load_tile_async(sBbuf[(c + 1) & 1], Xg + (size_t)(c + 1) * NC * D, tid);
            cp_commit();
        }

        const uint32_t aB = aBbuf[c & 1];
        float acc[2][4][4];
#pragma unroll
        for (int mt = 0; mt < 2; ++mt)
#pragma unroll
            for (int nt = 0; nt < 4; ++nt)
#pragma unroll
                for (int q = 0; q < 4; ++q) acc[mt][nt][q] = 0.0f;

#pragma unroll 4
        for (int ks = 0; ks < KSTEPS; ++ks) {
            const uint32_t koff = (uint32_t)(ks * 16 * 2);
            uint32_t a[2][4];
#pragma unroll
            for (int mt = 0; mt < 2; ++mt)
                ldsm_x4(a[mt][0], a[mt][1], a[mt][2], a[mt][3],
                        aA + (uint32_t)(mt * 16 * STRIDE * 2) + koff);
            uint32_t bfr[4][2];
#pragma unroll
            for (int p = 0; p < 2; ++p) {
                uint32_t r0, r1, r2, r3;
                ldsm_x4(r0, r1, r2, r3,
                        aB + (uint32_t)(p * 16 * STRIDE * 2) + koff);
                bfr[p * 2][0]     = r0; bfr[p * 2][1]     = r1;
                bfr[p * 2 + 1][0] = r2; bfr[p * 2 + 1][1] = r3;
            }
#pragma unroll
            for (int mt = 0; mt < 2; ++mt)
#pragma unroll
                for (int nt = 0; nt < 4; ++nt)
                    mma_bf16(acc[mt][nt][0], acc[mt][nt][1],
                             acc[mt][nt][2], acc[mt][nt][3],
                             a[mt][0], a[mt][1], a[mt][2], a[mt][3],
                             bfr[nt][0], bfr[nt][1]);
        }

        // fold chunk into running max (scale by 1/||x_s||)
#pragma unroll
        for (int nt = 0; nt < 4; ++nt) {
            const int n0 = c * NC + warp_n * 32 + nt * 8 + (lane & 3) * 2;
            const float i0 = s_ina[n0], i1 = s_ina[n0 + 1];
#pragma unroll
            for (int mt = 0; mt < 2; ++mt) {
                rmax[mt][0] = fmaxf(rmax[mt][0],
                                    fmaxf(acc[mt][nt][0] * i0, acc[mt][nt][1] * i1));
                rmax[mt][1] = fmaxf(rmax[mt][1],
                                    fmaxf(acc[mt][nt][2] * i0, acc[mt][nt][3] * i1));
            }
        }

        if (c + 1 < NCH) {
            cp_wait0();
            __syncthreads();
        }
    }

    // reduce over the 4 lanes (lane&3) sharing each m row
#pragma unroll
    for (int mt = 0; mt < 2; ++mt)
#pragma unroll
        for (int rh = 0; rh < 2; ++rh) {
            float v = rmax[mt][rh];
            v = fmaxf(v, __shfl_xor_sync(0xffffffffu, v, 1));
            v = fmaxf(v, __shfl_xor_sync(0xffffffffu, v, 2));
            rmax[mt][rh] = v;
        }
    __syncthreads();
    if ((lane & 3) == 0) {
#pragma unroll
        for (int mt = 0; mt < 2; ++mt)
#pragma unroll
            for (int rh = 0; rh < 2; ++rh) {
                const int m = warp_m * 32 + mt * 16 + rh * 8 + (lane >> 2);
                red[warp_n * MT + m] = rmax[mt][rh];
            }
    }
    __syncthreads();
    if (tid < MT) {
        float v = fmaxf(fmaxf(red[tid], red[MT + tid]),
                        fmaxf(red[2 * MT + tid], red[3 * MT + tid]));
        const int m = m0 + tid;
        g_simmax[b * SM_ + m] = v * g_inv_nb[b * SM_ + m];
    }
}

// ---------------------------------------------------------------------------
// 3) approx top-8 per batch: register-resident, warp-shuffle argmax rounds
// ---------------------------------------------------------------------------
__global__ __launch_bounds__(512)
void top8_kernel() {
    __shared__ float swv[16];
    __shared__ int   swi[16];
    __shared__ int   s_win;

    const int b    = blockIdx.x;
    const int tid  = threadIdx.x;
    const int wid  = tid >> 5;
    const int lane = tid & 31;

    float e[8];
#pragma unroll
    for (int j = 0; j < 8; ++j) e[j] = g_simmax[b * SM_ + tid * 8 + j];

    for (int k = 0; k < NCAND; ++k) {
        float bv = e[0];
        int   bi = tid * 8;
#pragma unroll
        for (int j = 1; j < 8; ++j)
            if (e[j] > bv) { bv = e[j]; bi = tid * 8 + j; }
#pragma unroll
        for (int off = 16; off; off >>= 1) {
            float ov = __shfl_xor_sync(0xffffffffu, bv, off);
            int   oi = __shfl_xor_sync(0xffffffffu, bi, off);
            if (ov > bv || (ov == bv && oi < bi)) { bv = ov; bi = oi; }
        }
        if (lane == 0) { swv[wid] = bv; swi[wid] = bi; }
        __syncthreads();
        if (wid == 0) {
            float fv = (lane < 16) ? swv[lane] : NEG_INF;
            int   fi = (lane < 16) ? swi[lane] : 0x7fffffff;
#pragma unroll
            for (int off = 8; off; off >>= 1) {
                float ov = __shfl_xor_sync(0xffffffffu, fv, off);
                int   oi = __shfl_xor_sync(0xffffffffu, fi, off);
                if (ov > fv || (ov == fv && oi < fi)) { fv = ov; fi = oi; }
            }
            if (lane == 0) {
                s_win = fi;
                g_cand[b * NCAND + k] = fi;
            }
        }
        __syncthreads();
        const int w = s_win;
        if ((w >> 3) == tid) e[w & 7] = NEG_INF;
    }
}

// ---------------------------------------------------------------------------
// 4) exact fp32 re-rank of the 8 candidates, pick top-5, gather rows + indices
// ---------------------------------------------------------------------------
__global__ __launch_bounds__(256)
void rerank_kernel(const float* __restrict__ x, const float* __restrict__ mem,
                   float* __restrict__ out) {
    __shared__ float s_m[NCAND][D];
    __shared__ float s_x[32][D + 1];
    __shared__ float s_score[NCAND];
    __shared__ int   s_sel[TOPK];

    const int b    = blockIdx.x;
    const int tid  = threadIdx.x;
    const int wid  = tid >> 5;
    const int lane = tid & 31;

    for (int i = tid; i < NCAND * D; i += 256) {
        int c = i >> 8, d = i & 255;
        s_m[c][d] = mem[((size_t)b * SM_ + g_cand[b * NCAND + c]) * D + d];
    }

    float vmax = NEG_INF;
    for (int s0 = 0; s0 < SX; s0 += 32) {
        __syncthreads();
        for (int i = tid; i < 32 * D; i += 256) {
            int r = i >> 8, d = i & 255;
            s_x[r][d] = x[((size_t)b * SX + s0 + r) * D + d];
        }
        __syncthreads();
        float dot = 0.0f;
#pragma unroll 8
        for (int d = 0; d < D; ++d)
            dot = fmaf(s_x[lane][d], s_m[wid][d], dot);
        vmax = fmaxf(vmax, dot * g_inv_na[b * SX + s0 + lane]);
    }
#pragma unroll
    for (int off = 16; off; off >>= 1)
        vmax = fmaxf(vmax, __shfl_xor_sync(0xffffffffu, vmax, off));
    if (lane == 0)
        s_score[wid] = vmax * g_inv_nb[b * SM_ + g_cand[b * NCAND + wid]];
    __syncthreads();

    if (tid == 0) {
        float sc[NCAND];
        int   ix[NCAND];
        for (int i = 0; i < NCAND; ++i) {
            sc[i] = s_score[i];
            ix[i] = g_cand[b * NCAND + i];
        }
        for (int k = 0; k < TOPK; ++k) {
            int best = k;
            for (int j = k + 1; j < NCAND; ++j)
                if (sc[j] > sc[best] || (sc[j] == sc[best] && ix[j] < ix[best])) best = j;
            float ts = sc[k]; sc[k] = sc[best]; sc[best] = ts;
            int   ti = ix[k]; ix[k] = ix[best]; ix[best] = ti;
            s_sel[k] = ix[k];
        }
    }
    __syncthreads();

    for (int k = 0; k < TOPK; ++k)
        out[(size_t)k * B * D + (size_t)b * D + tid] =
            mem[((size_t)b * SM_ + s_sel[k]) * D + tid];
    if (tid < TOPK)
        out[(size_t)TOPK * B * D + b * TOPK + tid] = (float)s_sel[tid];
}

// ---------------------------------------------------------------------------
extern "C" void kernel_launch(void* const* d_in, const int* in_sizes, int n_in,
                              void* d_out, int out_size) {
    const float* x   = (const float*)d_in[0];   // [B, SX, D]
    const float* mem = (const float*)d_in[1];   // [B, SM, D]
    float* out = (float*)d_out;
    (void)in_sizes; (void)n_in; (void)out_size;

    invnorm_kernel<<<(B * SX) / 8, 256>>>(x, B * SX, 0);
    invnorm_kernel<<<(B * SM_) / 8, 256>>>(mem, B * SM_, 1);

    const int smem_bytes = (MT * STRIDE + 2 * NC * STRIDE) * 2 + (SX + 4 * MT) * 4; // ~207 KB
    static bool attr_set = false;   // idempotent attribute, not work caching
    if (!attr_set) {
        cudaFuncSetAttribute(simmax_mma_kernel,
                             cudaFuncAttributeMaxDynamicSharedMemorySize, smem_bytes);
        attr_set = true;
    }
    dim3 grid(SM_ / MT, B);
    simmax_mma_kernel<<<grid, NTHREADS, smem_bytes>>>();

    top8_kernel<<<B, 512>>>();
    rerank_kernel<<<B, 256>>>(x, mem, out);
}